// round 10
// baseline (speedup 1.0000x reference)
#include <cuda_runtime.h>
#include <cuda_fp16.h>
#include <cstdint>

// ---------------- problem constants ----------------
#define EDGE_DIM 32
#define MID      64
#define NCIN     32
#define NCOUT    32
#define MO       3
#define QDIM     96
#define RADW     3072
#define EMAX     32768
#define NCHUNK   32
#define HP       68            // h overlay pitch (floats)

// scratch: per chunk 12288 B fragment-register-order fp16 W3 image
__device__ __half g_B[NCHUNK * 12288 / 2];

// ---------------- helpers ----------------
__device__ __forceinline__ float gelu_exact(float x) {
    return 0.5f * x * (1.0f + erff(x * 0.70710678118654752440f));
}
__device__ __forceinline__ float warp_allreduce_sum(float v) {
    v += __shfl_xor_sync(0xffffffffu, v, 16);
    v += __shfl_xor_sync(0xffffffffu, v, 8);
    v += __shfl_xor_sync(0xffffffffu, v, 4);
    v += __shfl_xor_sync(0xffffffffu, v, 2);
    v += __shfl_xor_sync(0xffffffffu, v, 1);
    return v;
}
__device__ __forceinline__ uint32_t pack_h2(float x, float y) {
    half2 h = __floats2half2_rn(x, y);
    return *(uint32_t*)&h;
}
__device__ __forceinline__ void mma16816(float c[4], const uint32_t a[4],
                                         uint32_t b0, uint32_t b1) {
    asm volatile(
        "mma.sync.aligned.m16n8k16.row.col.f32.f16.f16.f32 "
        "{%0,%1,%2,%3}, {%4,%5,%6,%7}, {%8,%9}, {%0,%1,%2,%3};"
        : "+f"(c[0]), "+f"(c[1]), "+f"(c[2]), "+f"(c[3])
        : "r"(a[0]), "r"(a[1]), "r"(a[2]), "r"(a[3]), "r"(b0), "r"(b1));
}

// ---------------- Kernel P: W3 -> fragment-register-order fp16 image ----------
__global__ void __launch_bounds__(256) prep_w3(const float* __restrict__ W3) {
    int idx = blockIdx.x * 256 + threadIdx.x;     // over 64*3072
    if (idx >= MID * RADW) return;
    int k = idx / RADW, n = idx % RADW;
    int chunk = n / QDIM, nl = n % QDIM;
    int ng = nl / 48, nq = nl % 48;
    int nt = nq >> 3, rr = nq & 7;
    int kt = k >> 4, kk = k & 15;
    int cc = (kk >> 1) & 3, bb = kk >> 3, hp = kk & 1;
    int lane = rr * 4 + cc;
    int j = kt * 3 + (nt >> 1);
    int r4 = ((nt & 1) << 1) + bb;
    int off = chunk * 12288 + ng * 6144 + j * 512 + lane * 16 + r4 * 4 + hp * 2;
    g_B[off >> 1] = __float2half_rn(W3[idx]);
}

// ---------------- Kernel M: fused MLP + mma.sync fp16 GEMM + rw@T ----------------
// 256 thr / 8 warps = 4 edge-groups x 2 n-halves; 128 edges per CTA; 2 CTAs/SM.
// T layout: [qp 48][e 128], pitch 2080 B (conflict-free both directions).
#define SM_B     0                          // 12288 (single buffer)
#define SM_T     12288                      // 48 x 2080 = 99840 -> 112128
#define SM_PED   112128                     // 1536 -> 113664
#define SM_TOTAL 113664
#define TPITCH   2080

__global__ void __launch_bounds__(256, 2) pair_main_kernel(
    const float* __restrict__ edges,
    const float* __restrict__ feats,
    const float* __restrict__ basis,
    const float* __restrict__ W1, const float* __restrict__ b1,
    const float* __restrict__ g1, const float* __restrict__ be1,
    const float* __restrict__ W2, const float* __restrict__ b2,
    const float* __restrict__ g2, const float* __restrict__ be2,
    float* __restrict__ out,
    int E)
{
    extern __shared__ __align__(1024) char smem[];
    const int tid = threadIdx.x, w = tid >> 5, lane = tid & 31;
    const int r = lane >> 2, c = lane & 3;
    const int eg = w >> 1, ng = w & 1;
    const int E0 = blockIdx.x * 128;
    const int ebase = eg * 32 + r;

    // prologue overlays inside the T region (dead before T is built)
    float* Wsm = (float*)(smem + SM_T);           // 26112 B
    float* hsm = (float*)(smem + SM_T + 26112);   // 128*68*4 = 34816 B
    float* W1s = Wsm;               // 2048 floats
    float* W2s = Wsm + 2048;        // 4096 floats
    float* prm = Wsm + 6144;        // 384 floats

    // ---- load MLP weights ----
    for (int i = tid; i < EDGE_DIM * MID; i += 256) W1s[i] = W1[i];
    for (int i = tid; i < MID * MID; i += 256)      W2s[i] = W2[i];
    if (tid < MID) {
        prm[tid] = b1[tid]; prm[MID + tid] = g1[tid]; prm[2*MID + tid] = be1[tid];
        prm[3*MID + tid] = b2[tid]; prm[4*MID + tid] = g2[tid]; prm[5*MID + tid] = be2[tid];
    }
    __syncthreads();

    // ---- fused MLP: warp w computes edges [w*16, w*16+16) ----
    for (int it = 0; it < 16; it++) {
        const int el = w * 16 + it;
        const float xv = edges[(size_t)(E0 + el) * EDGE_DIM + lane];
        float a0 = prm[lane], a1 = prm[lane + 32];
        #pragma unroll
        for (int k = 0; k < 32; k++) {
            const float xk = __shfl_sync(0xffffffffu, xv, k);
            a0 = fmaf(xk, W1s[k * MID + lane], a0);
            a1 = fmaf(xk, W1s[k * MID + lane + 32], a1);
        }
        float mean = warp_allreduce_sum(a0 + a1) * (1.0f / 64.0f);
        float d0 = a0 - mean, d1 = a1 - mean;
        float var = warp_allreduce_sum(d0 * d0 + d1 * d1) * (1.0f / 64.0f);
        float inv = rsqrtf(var + 1e-5f);
        a0 = gelu_exact(d0 * inv * prm[MID + lane]      + prm[2*MID + lane]);
        a1 = gelu_exact(d1 * inv * prm[MID + lane + 32] + prm[2*MID + lane + 32]);
        float c0 = prm[3*MID + lane], c1 = prm[3*MID + lane + 32];
        #pragma unroll
        for (int k = 0; k < 32; k++) {
            const float u  = __shfl_sync(0xffffffffu, a0, k);
            const float v2 = __shfl_sync(0xffffffffu, a1, k);
            c0 = fmaf(u,  W2s[k * MID + lane], c0);
            c0 = fmaf(v2, W2s[(k + 32) * MID + lane], c0);
            c1 = fmaf(u,  W2s[k * MID + lane + 32], c1);
            c1 = fmaf(v2, W2s[(k + 32) * MID + lane + 32], c1);
        }
        mean = warp_allreduce_sum(c0 + c1) * (1.0f / 64.0f);
        d0 = c0 - mean; d1 = c1 - mean;
        var = warp_allreduce_sum(d0 * d0 + d1 * d1) * (1.0f / 64.0f);
        inv = rsqrtf(var + 1e-5f);
        c0 = gelu_exact(d0 * inv * prm[4*MID + lane]      + prm[5*MID + lane]);
        c1 = gelu_exact(d1 * inv * prm[4*MID + lane + 32] + prm[5*MID + lane + 32]);
        hsm[el * HP + lane]      = c0;
        hsm[el * HP + lane + 32] = c1;
    }
    __syncthreads();

    // ---- A fragments from h overlay ----
    uint32_t A[2][4][4];
    #pragma unroll
    for (int mt = 0; mt < 2; mt++) {
        const float* h0 = hsm + (ebase + mt * 16) * HP;
        const float* h1 = hsm + (ebase + mt * 16 + 8) * HP;
        #pragma unroll
        for (int kt = 0; kt < 4; kt++) {
            const int k0 = kt * 16 + 2 * c;
            float2 p0 = *(const float2*)(h0 + k0);
            float2 p1 = *(const float2*)(h0 + k0 + 8);
            float2 p2 = *(const float2*)(h1 + k0);
            float2 p3 = *(const float2*)(h1 + k0 + 8);
            A[mt][kt][0] = pack_h2(p0.x, p0.y);
            A[mt][kt][1] = pack_h2(p2.x, p2.y);
            A[mt][kt][2] = pack_h2(p1.x, p1.y);
            A[mt][kt][3] = pack_h2(p3.x, p3.y);
        }
    }
    __syncthreads();   // all h reads done; T may overwrite overlay

    // ---- T tile build: [qp][e], e-major per thread batch (conflict-free STS) ----
    for (int idx = tid; idx < 48 * 128; idx += 256) {
        const int qp = idx >> 7, e = idx & 127;
        const int q0 = 2 * qp, q1 = q0 + 1;
        const int i0 = q0 / 3, f0 = q0 % 3, i1 = q1 / 3, f1 = q1 % 3;
        const float* fe = feats + (size_t)(E0 + e) * (NCIN * 3);
        const float* be = basis + (size_t)(E0 + e) * 27;
        const float a0 = fe[i0*3], a1 = fe[i0*3+1], a2 = fe[i0*3+2];
        const float b0 = fe[i1*3], b1v = fe[i1*3+1], b2v = fe[i1*3+2];
        float t0[3], t1[3];
        #pragma unroll
        for (int m = 0; m < 3; m++) {
            t0[m] = a0 * be[f0*3+m] + a1  * be[9 + f0*3+m] + a2  * be[18 + f0*3+m];
            t1[m] = b0 * be[f1*3+m] + b1v * be[9 + f1*3+m] + b2v * be[18 + f1*3+m];
        }
        uint4 v;
        v.x = pack_h2(t0[0], t0[1]);
        v.y = pack_h2(t0[2], 0.0f);
        v.z = pack_h2(t1[0], t1[1]);
        v.w = pack_h2(t1[2], 0.0f);
        *(uint4*)(smem + SM_T + qp * TPITCH + e * 16) = v;
    }

    // ---- stage chunk 0 ----
    const float4* gB4 = (const float4*)g_B;
    {
        float4* d = (float4*)(smem + SM_B);
        #pragma unroll
        for (int j = 0; j < 3; j++) d[tid + j * 256] = gB4[tid + j * 256];
    }
    __syncthreads();

    float* ped = (float*)(smem + SM_PED);
    const char* buf = smem + SM_B + ng * 6144;

    for (int o = 0; o < NCHUNK; o++) {
        // prefetch next chunk into regs
        float4 stg[3];
        if (o + 1 < NCHUNK) {
            #pragma unroll
            for (int j = 0; j < 3; j++)
                stg[j] = gB4[(size_t)(o + 1) * 768 + tid + j * 256];
        }

        float C[2][6][4];
        #pragma unroll
        for (int mt = 0; mt < 2; mt++)
            #pragma unroll
            for (int nt = 0; nt < 6; nt++) {
                C[mt][nt][0] = 0.f; C[mt][nt][1] = 0.f;
                C[mt][nt][2] = 0.f; C[mt][nt][3] = 0.f;
            }

        #pragma unroll
        for (int kt = 0; kt < 4; kt++) {
            uint4 bh[3];
            #pragma unroll
            for (int jj = 0; jj < 3; jj++)
                bh[jj] = *(const uint4*)(buf + (kt*3 + jj) * 512 + lane * 16);
            #pragma unroll
            for (int jj = 0; jj < 3; jj++) {
                #pragma unroll
                for (int mt = 0; mt < 2; mt++) {
                    mma16816(C[mt][2*jj],   A[mt][kt], bh[jj].x, bh[jj].y);
                    mma16816(C[mt][2*jj+1], A[mt][kt], bh[jj].z, bh[jj].w);
                }
            }
        }

        // ---- epilogue ----
        float acc[4][3];
        #pragma unroll
        for (int s = 0; s < 4; s++) { acc[s][0]=0.f; acc[s][1]=0.f; acc[s][2]=0.f; }

        #pragma unroll
        for (int nt = 0; nt < 6; nt++) {
            const int qp = ng * 24 + nt * 4 + c;
            #pragma unroll
            for (int s = 0; s < 4; s++) {
                const int es = ebase + 8 * s;
                uint4 tv = *(const uint4*)(smem + SM_T + qp * TPITCH + es * 16);
                float2 u0 = __half22float2(*(half2*)&tv.x);
                float2 u1 = __half22float2(*(half2*)&tv.y);
                float2 u2 = __half22float2(*(half2*)&tv.z);
                float2 u3 = __half22float2(*(half2*)&tv.w);
                const float cA = C[s >> 1][nt][(s & 1) * 2];
                const float cB = C[s >> 1][nt][(s & 1) * 2 + 1];
                acc[s][0] = fmaf(cA, u0.x, fmaf(cB, u2.x, acc[s][0]));
                acc[s][1] = fmaf(cA, u0.y, fmaf(cB, u2.y, acc[s][1]));
                acc[s][2] = fmaf(cA, u1.x, fmaf(cB, u3.x, acc[s][2]));
            }
        }
        #pragma unroll
        for (int s = 0; s < 4; s++) {
            #pragma unroll
            for (int m = 0; m < 3; m++) {
                acc[s][m] += __shfl_xor_sync(0xffffffffu, acc[s][m], 1);
                acc[s][m] += __shfl_xor_sync(0xffffffffu, acc[s][m], 2);
            }
        }

        // ng=1 publishes partials (single parity: consumed before next publish)
        if (ng == 1 && c == 0) {
            float* p = ped + (eg * 8 + r) * 12;
            #pragma unroll
            for (int s = 0; s < 4; s++) {
                p[s*3+0] = acc[s][0]; p[s*3+1] = acc[s][1]; p[s*3+2] = acc[s][2];
            }
        }
        __syncthreads();   // B reads done, ped published

        // ng=0 combines + stores; others refill B
        if (ng == 0 && c == 0) {
            const float* p = ped + (eg * 8 + r) * 12;
            #pragma unroll
            for (int s = 0; s < 4; s++) {
                float* op = out + (size_t)(E0 + ebase + 8*s) * (NCOUT * MO) + o * 3;
                op[0] = acc[s][0] + p[s*3+0];
                op[1] = acc[s][1] + p[s*3+1];
                op[2] = acc[s][2] + p[s*3+2];
            }
        }
        if (o + 1 < NCHUNK) {
            float4* d = (float4*)(smem + SM_B);
            #pragma unroll
            for (int j = 0; j < 3; j++) d[tid + j * 256] = stg[j];
        }
        __syncthreads();   // new B visible; ped consumed
    }
}

// ---------------- launch ----------------
extern "C" void kernel_launch(void* const* d_in, const int* in_sizes, int n_in,
                              void* d_out, int out_size) {
    const float* edges = (const float*)d_in[0];
    const float* feats = (const float*)d_in[1];
    const float* basis = (const float*)d_in[2];
    const float* W1    = (const float*)d_in[3];
    const float* b1    = (const float*)d_in[4];
    const float* g1    = (const float*)d_in[5];
    const float* be1   = (const float*)d_in[6];
    const float* W2    = (const float*)d_in[7];
    const float* b2    = (const float*)d_in[8];
    const float* g2    = (const float*)d_in[9];
    const float* be2   = (const float*)d_in[10];
    const float* W3    = (const float*)d_in[11];
    float* out = (float*)d_out;

    const int E = in_sizes[0] / EDGE_DIM;

    prep_w3<<<(MID * RADW + 255) / 256, 256>>>(W3);

    cudaFuncSetAttribute(pair_main_kernel,
                         cudaFuncAttributeMaxDynamicSharedMemorySize, SM_TOTAL);
    pair_main_kernel<<<E / 128, 256, SM_TOTAL>>>(edges, feats, basis,
                                                 W1, b1, g1, be1,
                                                 W2, b2, g2, be2, out, E);
}

// round 11
// speedup vs baseline: 1.5005x; 1.5005x over previous
#include <cuda_runtime.h>
#include <cuda_fp16.h>
#include <cstdint>

// ---------------- problem constants ----------------
#define EDGE_DIM 32
#define MID      64
#define NCIN     32
#define NCOUT    32
#define MO       3
#define QDIM     96
#define RADW     3072
#define EMAX     32768
#define NCHUNK   32
#define HP       68            // h smem pitch (floats)

// scratch: per chunk 12288 B fragment-register-order fp16 W3 image
__device__ __half g_B[NCHUNK * 12288 / 2];

// ---------------- helpers ----------------
__device__ __forceinline__ float gelu_exact(float x) {
    return 0.5f * x * (1.0f + erff(x * 0.70710678118654752440f));
}
__device__ __forceinline__ float warp_allreduce_sum(float v) {
    v += __shfl_xor_sync(0xffffffffu, v, 16);
    v += __shfl_xor_sync(0xffffffffu, v, 8);
    v += __shfl_xor_sync(0xffffffffu, v, 4);
    v += __shfl_xor_sync(0xffffffffu, v, 2);
    v += __shfl_xor_sync(0xffffffffu, v, 1);
    return v;
}
__device__ __forceinline__ uint32_t pack_h2(float x, float y) {
    half2 h = __floats2half2_rn(x, y);
    return *(uint32_t*)&h;
}
__device__ __forceinline__ void mma16816(float c[4], const uint32_t a[4],
                                         uint32_t b0, uint32_t b1) {
    asm volatile(
        "mma.sync.aligned.m16n8k16.row.col.f32.f16.f16.f32 "
        "{%0,%1,%2,%3}, {%4,%5,%6,%7}, {%8,%9}, {%0,%1,%2,%3};"
        : "+f"(c[0]), "+f"(c[1]), "+f"(c[2]), "+f"(c[3])
        : "r"(a[0]), "r"(a[1]), "r"(a[2]), "r"(a[3]), "r"(b0), "r"(b1));
}

// ---------------- Kernel P: W3 -> fragment-register-order fp16 image ----------
__global__ void __launch_bounds__(256) prep_w3(const float* __restrict__ W3) {
    int idx = blockIdx.x * 256 + threadIdx.x;     // over 64*3072
    if (idx >= MID * RADW) return;
    int k = idx / RADW, n = idx % RADW;
    int chunk = n / QDIM, nl = n % QDIM;
    int ng = nl / 48, nq = nl % 48;
    int nt = nq >> 3, rr = nq & 7;
    int kt = k >> 4, kk = k & 15;
    int cc = (kk >> 1) & 3, bb = kk >> 3, hp = kk & 1;
    int lane = rr * 4 + cc;
    int j = kt * 3 + (nt >> 1);
    int r4 = ((nt & 1) << 1) + bb;
    int off = chunk * 12288 + ng * 6144 + j * 512 + lane * 16 + r4 * 4 + hp * 2;
    g_B[off >> 1] = __float2half_rn(W3[idx]);
}

// ---------------- Kernel M: fused MLP + mma.sync, 512 thr / 16 warps ----------------
// warp = 16 edges x 48 n; 8 edge-groups x 2 n-halves; 128 edges per CTA.
#define SM_B     0                          // 2 x 12288 = 24576
#define SM_T     24576                      // 128 x 832 = 106496 -> 131072
#define SM_PED   131072                     // 2 x 384 x 4 = 3072 -> 134144
#define SM_W     134144                     // 6528 floats = 26112 -> 160256
#define SM_H     160256                     // 128 x 68 x 4 = 34816 -> 195072
#define SM_TOTAL 195072

__global__ void __launch_bounds__(512, 1) pair_main_kernel(
    const float* __restrict__ edges,
    const float* __restrict__ feats,
    const float* __restrict__ basis,
    const float* __restrict__ W1, const float* __restrict__ b1,
    const float* __restrict__ g1, const float* __restrict__ be1,
    const float* __restrict__ W2, const float* __restrict__ b2,
    const float* __restrict__ g2, const float* __restrict__ be2,
    float* __restrict__ out,
    int E)
{
    extern __shared__ __align__(1024) char smem[];
    const int tid = threadIdx.x, w = tid >> 5, lane = tid & 31;
    const int r = lane >> 2, c = lane & 3;
    const int eg = w >> 1, ng = w & 1;        // eg in [0,8)
    const int E0 = blockIdx.x * 128;
    const int ebase = eg * 16 + r;

    float* hsm = (float*)(smem + SM_H);
    float* Wsm = (float*)(smem + SM_W);
    float* W1s = Wsm;               // 2048
    float* W2s = Wsm + 2048;        // 4096
    float* prm = Wsm + 6144;        // 384

    // ---- load MLP weights ----
    for (int i = tid; i < EDGE_DIM * MID; i += 512) W1s[i] = W1[i];
    for (int i = tid; i < MID * MID; i += 512)      W2s[i] = W2[i];
    if (tid < MID) {
        prm[tid] = b1[tid]; prm[MID + tid] = g1[tid]; prm[2*MID + tid] = be1[tid];
        prm[3*MID + tid] = b2[tid]; prm[4*MID + tid] = g2[tid]; prm[5*MID + tid] = be2[tid];
    }

    // ---- T tile: [e][qp] pitch 832; one uint4 = fp16 {t0, t1} ----
    for (int idx = tid; idx < 128 * 48; idx += 512) {
        const int e = idx / 48, qp = idx - e * 48;
        const int q0 = 2 * qp, q1 = q0 + 1;
        const int i0 = q0 / 3, f0 = q0 % 3, i1 = q1 / 3, f1 = q1 % 3;
        const float* fe = feats + (size_t)(E0 + e) * (NCIN * 3);
        const float* be = basis + (size_t)(E0 + e) * 27;
        const float a0 = fe[i0*3], a1 = fe[i0*3+1], a2 = fe[i0*3+2];
        const float b0 = fe[i1*3], b1v = fe[i1*3+1], b2v = fe[i1*3+2];
        float t0[3], t1[3];
        #pragma unroll
        for (int m = 0; m < 3; m++) {
            t0[m] = a0 * be[f0*3+m] + a1  * be[9 + f0*3+m] + a2  * be[18 + f0*3+m];
            t1[m] = b0 * be[f1*3+m] + b1v * be[9 + f1*3+m] + b2v * be[18 + f1*3+m];
        }
        uint4 v;
        v.x = pack_h2(t0[0], t0[1]);
        v.y = pack_h2(t0[2], 0.0f);
        v.z = pack_h2(t1[0], t1[1]);
        v.w = pack_h2(t1[2], 0.0f);
        *(uint4*)(smem + SM_T + e * 832 + qp * 16) = v;
    }

    // ---- stage chunk 0 (768 float4) ----
    const float4* gB4 = (const float4*)g_B;
    {
        float4* d = (float4*)(smem + SM_B);
        d[tid] = gB4[tid];
        if (tid < 256) d[512 + tid] = gB4[512 + tid];
    }
    __syncthreads();    // weights visible; T/B staged

    // ---- fused MLP: warp w computes edges [w*8, w*8+8) ----
    for (int it = 0; it < 8; it++) {
        const int el = w * 8 + it;
        const float xv = edges[(size_t)(E0 + el) * EDGE_DIM + lane];
        float a0 = prm[lane], a1 = prm[lane + 32];
        #pragma unroll
        for (int k = 0; k < 32; k++) {
            const float xk = __shfl_sync(0xffffffffu, xv, k);
            a0 = fmaf(xk, W1s[k * MID + lane], a0);
            a1 = fmaf(xk, W1s[k * MID + lane + 32], a1);
        }
        float mean = warp_allreduce_sum(a0 + a1) * (1.0f / 64.0f);
        float d0 = a0 - mean, d1 = a1 - mean;
        float var = warp_allreduce_sum(d0 * d0 + d1 * d1) * (1.0f / 64.0f);
        float inv = rsqrtf(var + 1e-5f);
        a0 = gelu_exact(d0 * inv * prm[MID + lane]      + prm[2*MID + lane]);
        a1 = gelu_exact(d1 * inv * prm[MID + lane + 32] + prm[2*MID + lane + 32]);
        float c0 = prm[3*MID + lane], c1 = prm[3*MID + lane + 32];
        #pragma unroll
        for (int k = 0; k < 32; k++) {
            const float u  = __shfl_sync(0xffffffffu, a0, k);
            const float v2 = __shfl_sync(0xffffffffu, a1, k);
            c0 = fmaf(u,  W2s[k * MID + lane], c0);
            c0 = fmaf(v2, W2s[(k + 32) * MID + lane], c0);
            c1 = fmaf(u,  W2s[k * MID + lane + 32], c1);
            c1 = fmaf(v2, W2s[(k + 32) * MID + lane + 32], c1);
        }
        mean = warp_allreduce_sum(c0 + c1) * (1.0f / 64.0f);
        d0 = c0 - mean; d1 = c1 - mean;
        var = warp_allreduce_sum(d0 * d0 + d1 * d1) * (1.0f / 64.0f);
        inv = rsqrtf(var + 1e-5f);
        c0 = gelu_exact(d0 * inv * prm[4*MID + lane]      + prm[5*MID + lane]);
        c1 = gelu_exact(d1 * inv * prm[4*MID + lane + 32] + prm[5*MID + lane + 32]);
        hsm[el * HP + lane]      = c0;
        hsm[el * HP + lane + 32] = c1;
    }
    __syncthreads();

    // ---- A fragments (16 edges: rows ebase, ebase+8) ----
    uint32_t A[4][4];
    {
        const float* h0 = hsm + ebase * HP;
        const float* h1 = hsm + (ebase + 8) * HP;
        #pragma unroll
        for (int kt = 0; kt < 4; kt++) {
            const int k0 = kt * 16 + 2 * c;
            float2 p0 = *(const float2*)(h0 + k0);
            float2 p1 = *(const float2*)(h0 + k0 + 8);
            float2 p2 = *(const float2*)(h1 + k0);
            float2 p3 = *(const float2*)(h1 + k0 + 8);
            A[kt][0] = pack_h2(p0.x, p0.y);
            A[kt][1] = pack_h2(p2.x, p2.y);
            A[kt][2] = pack_h2(p1.x, p1.y);
            A[kt][3] = pack_h2(p3.x, p3.y);
        }
    }

    float* ped = (float*)(smem + SM_PED);

    for (int o = 0; o < NCHUNK; o++) {
        // prefetch next chunk into regs
        float4 stg0, stg1;
        if (o + 1 < NCHUNK) {
            stg0 = gB4[(size_t)(o + 1) * 768 + tid];
            if (tid < 256) stg1 = gB4[(size_t)(o + 1) * 768 + 512 + tid];
        }

        const char* buf = smem + SM_B + (o & 1) * 12288 + ng * 6144;
        float C[6][4];
        #pragma unroll
        for (int nt = 0; nt < 6; nt++) {
            C[nt][0] = 0.f; C[nt][1] = 0.f; C[nt][2] = 0.f; C[nt][3] = 0.f;
        }

        #pragma unroll
        for (int kt = 0; kt < 4; kt++) {
            uint4 bh[3];
            #pragma unroll
            for (int jj = 0; jj < 3; jj++)
                bh[jj] = *(const uint4*)(buf + (kt*3 + jj) * 512 + lane * 16);
            #pragma unroll
            for (int jj = 0; jj < 3; jj++) {
                mma16816(C[2*jj],   A[kt], bh[jj].x, bh[jj].y);
                mma16816(C[2*jj+1], A[kt], bh[jj].z, bh[jj].w);
            }
        }

        // ---- epilogue: 2 edge slots (ebase, ebase+8) ----
        float acc[2][3];
        acc[0][0]=0.f; acc[0][1]=0.f; acc[0][2]=0.f;
        acc[1][0]=0.f; acc[1][1]=0.f; acc[1][2]=0.f;

        #pragma unroll
        for (int nt = 0; nt < 6; nt++) {
            const int qp = ng * 24 + nt * 4 + c;
            #pragma unroll
            for (int s = 0; s < 2; s++) {
                const int es = ebase + 8 * s;
                uint4 tv = *(const uint4*)(smem + SM_T + es * 832 + qp * 16);
                float2 u0 = __half22float2(*(half2*)&tv.x);
                float2 u1 = __half22float2(*(half2*)&tv.y);
                float2 u2 = __half22float2(*(half2*)&tv.z);
                float2 u3 = __half22float2(*(half2*)&tv.w);
                const float cA = C[nt][2*s];
                const float cB = C[nt][2*s + 1];
                acc[s][0] = fmaf(cA, u0.x, fmaf(cB, u2.x, acc[s][0]));
                acc[s][1] = fmaf(cA, u0.y, fmaf(cB, u2.y, acc[s][1]));
                acc[s][2] = fmaf(cA, u1.x, fmaf(cB, u3.x, acc[s][2]));
            }
        }
        #pragma unroll
        for (int s = 0; s < 2; s++) {
            #pragma unroll
            for (int m = 0; m < 3; m++) {
                acc[s][m] += __shfl_xor_sync(0xffffffffu, acc[s][m], 1);
                acc[s][m] += __shfl_xor_sync(0xffffffffu, acc[s][m], 2);
            }
        }

        // ng=1 publishes partials (parity o&1)
        if (ng == 1 && c == 0) {
            float* p = ped + (o & 1) * 384 + (eg * 8 + r) * 6;
            p[0] = acc[0][0]; p[1] = acc[0][1]; p[2] = acc[0][2];
            p[3] = acc[1][0]; p[4] = acc[1][1]; p[5] = acc[1][2];
        }

        // stage next buffer (other parity)
        if (o + 1 < NCHUNK) {
            float4* d = (float4*)(smem + SM_B + ((o + 1) & 1) * 12288);
            d[tid] = stg0;
            if (tid < 256) d[512 + tid] = stg1;
        }
        __syncthreads();

        // ng=0 combines + stores
        if (ng == 0 && c == 0) {
            const float* p = ped + (o & 1) * 384 + (eg * 8 + r) * 6;
            float* op0 = out + (size_t)(E0 + ebase) * (NCOUT * MO) + o * 3;
            op0[0] = acc[0][0] + p[0];
            op0[1] = acc[0][1] + p[1];
            op0[2] = acc[0][2] + p[2];
            float* op1 = out + (size_t)(E0 + ebase + 8) * (NCOUT * MO) + o * 3;
            op1[0] = acc[1][0] + p[3];
            op1[1] = acc[1][1] + p[4];
            op1[2] = acc[1][2] + p[5];
        }
    }
}

// ---------------- launch ----------------
extern "C" void kernel_launch(void* const* d_in, const int* in_sizes, int n_in,
                              void* d_out, int out_size) {
    const float* edges = (const float*)d_in[0];
    const float* feats = (const float*)d_in[1];
    const float* basis = (const float*)d_in[2];
    const float* W1    = (const float*)d_in[3];
    const float* b1    = (const float*)d_in[4];
    const float* g1    = (const float*)d_in[5];
    const float* be1   = (const float*)d_in[6];
    const float* W2    = (const float*)d_in[7];
    const float* b2    = (const float*)d_in[8];
    const float* g2    = (const float*)d_in[9];
    const float* be2   = (const float*)d_in[10];
    const float* W3    = (const float*)d_in[11];
    float* out = (float*)d_out;

    const int E = in_sizes[0] / EDGE_DIM;

    prep_w3<<<(MID * RADW + 255) / 256, 256>>>(W3);

    cudaFuncSetAttribute(pair_main_kernel,
                         cudaFuncAttributeMaxDynamicSharedMemorySize, SM_TOTAL);
    pair_main_kernel<<<E / 128, 512, SM_TOTAL>>>(edges, feats, basis,
                                                 W1, b1, g1, be1,
                                                 W2, b2, g2, be2, out, E);
}

// round 13
// speedup vs baseline: 1.6015x; 1.0673x over previous
#include <cuda_runtime.h>
#include <cuda_fp16.h>
#include <cstdint>

// ---------------- problem constants ----------------
#define EDGE_DIM 32
#define MID      64
#define NCIN     32
#define NCOUT    32
#define MO       3
#define QDIM     96
#define RADW     3072
#define EMAX     32768
#define NCHUNK   32
#define HP       68            // h smem pitch (floats)

// scratch: per chunk 12288 B fragment-register-order fp16 W3 image
__device__ __half g_B[NCHUNK * 12288 / 2];

// ---------------- helpers ----------------
__device__ __forceinline__ float gelu_exact(float x) {
    return 0.5f * x * (1.0f + erff(x * 0.70710678118654752440f));
}
__device__ __forceinline__ float warp_allreduce_sum(float v) {
    v += __shfl_xor_sync(0xffffffffu, v, 16);
    v += __shfl_xor_sync(0xffffffffu, v, 8);
    v += __shfl_xor_sync(0xffffffffu, v, 4);
    v += __shfl_xor_sync(0xffffffffu, v, 2);
    v += __shfl_xor_sync(0xffffffffu, v, 1);
    return v;
}
__device__ __forceinline__ uint32_t pack_h2(float x, float y) {
    half2 h = __floats2half2_rn(x, y);
    return *(uint32_t*)&h;
}
__device__ __forceinline__ void mma16816(float c[4], const uint32_t a[4],
                                         uint32_t b0, uint32_t b1) {
    asm volatile(
        "mma.sync.aligned.m16n8k16.row.col.f32.f16.f16.f32 "
        "{%0,%1,%2,%3}, {%4,%5,%6,%7}, {%8,%9}, {%0,%1,%2,%3};"
        : "+f"(c[0]), "+f"(c[1]), "+f"(c[2]), "+f"(c[3])
        : "r"(a[0]), "r"(a[1]), "r"(a[2]), "r"(a[3]), "r"(b0), "r"(b1));
}
__device__ __forceinline__ void cp_async16(uint32_t smem_dst, const void* gsrc) {
    asm volatile("cp.async.cg.shared.global [%0], [%1], 16;"
                 :: "r"(smem_dst), "l"(gsrc) : "memory");
}

// ---------------- Kernel P: W3 -> fragment-register-order fp16 image ----------
__global__ void __launch_bounds__(256) prep_w3(const float* __restrict__ W3) {
    int idx = blockIdx.x * 256 + threadIdx.x;     // over 64*3072
    if (idx >= MID * RADW) return;
    int k = idx / RADW, n = idx % RADW;
    int chunk = n / QDIM, nl = n % QDIM;
    int ng = nl / 48, nq = nl % 48;
    int nt = nq >> 3, rr = nq & 7;
    int kt = k >> 4, kk = k & 15;
    int cc = (kk >> 1) & 3, bb = kk >> 3, hp = kk & 1;
    int lane = rr * 4 + cc;
    int j = kt * 3 + (nt >> 1);
    int r4 = ((nt & 1) << 1) + bb;
    int off = chunk * 12288 + ng * 6144 + j * 512 + lane * 16 + r4 * 4 + hp * 2;
    g_B[off >> 1] = __float2half_rn(W3[idx]);
}

// ---------------- Kernel M: fused MLP + mma.sync, 512 thr / 16 warps ----------------
// warp = 16 edges x 48 n; 8 edge-groups x 2 n-halves; 128 edges per CTA.
#define SM_B     0                          // 2 x 12288 = 24576
#define SM_T     24576                      // 128 x 832 = 106496 -> 131072
#define SM_PED   131072                     // 2 x 384 x 4 = 3072 -> 134144
#define SM_W     134144                     // 6528 floats = 26112 -> 160256
#define SM_H     160256                     // 128 x 68 x 4 = 34816 -> 195072
#define SM_TOTAL 195072

__global__ void __launch_bounds__(512, 1) pair_main_kernel(
    const float* __restrict__ edges,
    const float* __restrict__ feats,
    const float* __restrict__ basis,
    const float* __restrict__ W1, const float* __restrict__ b1,
    const float* __restrict__ g1, const float* __restrict__ be1,
    const float* __restrict__ W2, const float* __restrict__ b2,
    const float* __restrict__ g2, const float* __restrict__ be2,
    float* __restrict__ out,
    int E)
{
    extern __shared__ __align__(1024) char smem[];
    const uint32_t smem_u32 = (uint32_t)__cvta_generic_to_shared(smem);
    const int tid = threadIdx.x, w = tid >> 5, lane = tid & 31;
    const int r = lane >> 2, c = lane & 3;
    const int eg = w >> 1, ng = w & 1;        // eg in [0,8)
    const int E0 = blockIdx.x * 128;
    const int ebase = eg * 16 + r;

    float* hsm = (float*)(smem + SM_H);
    float* Wsm = (float*)(smem + SM_W);
    float* W1s = Wsm;               // 2048
    float* W2s = Wsm + 2048;        // 4096
    float* prm = Wsm + 6144;        // 384

    const float4* gB4 = (const float4*)g_B;

    // ---- stage chunk 0 via cp.async (overlaps all prologue work) ----
    {
        cp_async16(smem_u32 + SM_B + tid * 16, gB4 + tid);
        if (tid < 256)
            cp_async16(smem_u32 + SM_B + (512 + tid) * 16, gB4 + 512 + tid);
        asm volatile("cp.async.commit_group;" ::: "memory");
    }

    // ---- load MLP weights ----
    for (int i = tid; i < EDGE_DIM * MID; i += 512) W1s[i] = W1[i];
    for (int i = tid; i < MID * MID; i += 512)      W2s[i] = W2[i];
    if (tid < MID) {
        prm[tid] = b1[tid]; prm[MID + tid] = g1[tid]; prm[2*MID + tid] = be1[tid];
        prm[3*MID + tid] = b2[tid]; prm[4*MID + tid] = g2[tid]; prm[5*MID + tid] = be2[tid];
    }

    // ---- T tile: [e][qp] pitch 832; one uint4 = fp16 {t0, t1} ----
    for (int idx = tid; idx < 128 * 48; idx += 512) {
        const int e = idx / 48, qp = idx - e * 48;
        const int q0 = 2 * qp, q1 = q0 + 1;
        const int i0 = q0 / 3, f0 = q0 % 3, i1 = q1 / 3, f1 = q1 % 3;
        const float* fe = feats + (size_t)(E0 + e) * (NCIN * 3);
        const float* be = basis + (size_t)(E0 + e) * 27;
        const float a0 = fe[i0*3], a1 = fe[i0*3+1], a2 = fe[i0*3+2];
        const float b0 = fe[i1*3], b1v = fe[i1*3+1], b2v = fe[i1*3+2];
        float t0[3], t1[3];
        #pragma unroll
        for (int m = 0; m < 3; m++) {
            t0[m] = a0 * be[f0*3+m] + a1  * be[9 + f0*3+m] + a2  * be[18 + f0*3+m];
            t1[m] = b0 * be[f1*3+m] + b1v * be[9 + f1*3+m] + b2v * be[18 + f1*3+m];
        }
        uint4 v;
        v.x = pack_h2(t0[0], t0[1]);
        v.y = pack_h2(t0[2], 0.0f);
        v.z = pack_h2(t1[0], t1[1]);
        v.w = pack_h2(t1[2], 0.0f);
        *(uint4*)(smem + SM_T + e * 832 + qp * 16) = v;
    }
    __syncthreads();    // weights + T visible

    // ---- fused MLP: warp w computes edges [w*8, w*8+8) ----
    for (int it = 0; it < 8; it++) {
        const int el = w * 8 + it;
        const float xv = edges[(size_t)(E0 + el) * EDGE_DIM + lane];
        float a0 = prm[lane], a1 = prm[lane + 32];
        #pragma unroll
        for (int k = 0; k < 32; k++) {
            const float xk = __shfl_sync(0xffffffffu, xv, k);
            a0 = fmaf(xk, W1s[k * MID + lane], a0);
            a1 = fmaf(xk, W1s[k * MID + lane + 32], a1);
        }
        float mean = warp_allreduce_sum(a0 + a1) * (1.0f / 64.0f);
        float d0 = a0 - mean, d1 = a1 - mean;
        float var = warp_allreduce_sum(d0 * d0 + d1 * d1) * (1.0f / 64.0f);
        float inv = rsqrtf(var + 1e-5f);
        a0 = gelu_exact(d0 * inv * prm[MID + lane]      + prm[2*MID + lane]);
        a1 = gelu_exact(d1 * inv * prm[MID + lane + 32] + prm[2*MID + lane + 32]);
        float c0 = prm[3*MID + lane], c1 = prm[3*MID + lane + 32];
        #pragma unroll
        for (int k = 0; k < 32; k++) {
            const float u  = __shfl_sync(0xffffffffu, a0, k);
            const float v2 = __shfl_sync(0xffffffffu, a1, k);
            c0 = fmaf(u,  W2s[k * MID + lane], c0);
            c0 = fmaf(v2, W2s[(k + 32) * MID + lane], c0);
            c1 = fmaf(u,  W2s[k * MID + lane + 32], c1);
            c1 = fmaf(v2, W2s[(k + 32) * MID + lane + 32], c1);
        }
        mean = warp_allreduce_sum(c0 + c1) * (1.0f / 64.0f);
        d0 = c0 - mean; d1 = c1 - mean;
        var = warp_allreduce_sum(d0 * d0 + d1 * d1) * (1.0f / 64.0f);
        inv = rsqrtf(var + 1e-5f);
        c0 = gelu_exact(d0 * inv * prm[4*MID + lane]      + prm[5*MID + lane]);
        c1 = gelu_exact(d1 * inv * prm[4*MID + lane + 32] + prm[5*MID + lane + 32]);
        hsm[el * HP + lane]      = c0;
        hsm[el * HP + lane + 32] = c1;
    }
    asm volatile("cp.async.wait_group 0;" ::: "memory");
    __syncthreads();    // h visible; B chunk0 landed

    // ---- A fragments (16 edges: rows ebase, ebase+8) ----
    uint32_t A[4][4];
    {
        const float* h0 = hsm + ebase * HP;
        const float* h1 = hsm + (ebase + 8) * HP;
        #pragma unroll
        for (int kt = 0; kt < 4; kt++) {
            const int k0 = kt * 16 + 2 * c;
            float2 p0 = *(const float2*)(h0 + k0);
            float2 p1 = *(const float2*)(h0 + k0 + 8);
            float2 p2 = *(const float2*)(h1 + k0);
            float2 p3 = *(const float2*)(h1 + k0 + 8);
            A[kt][0] = pack_h2(p0.x, p0.y);
            A[kt][1] = pack_h2(p2.x, p2.y);
            A[kt][2] = pack_h2(p1.x, p1.y);
            A[kt][3] = pack_h2(p3.x, p3.y);
        }
    }

    // ---- T register cache for s=0, converted to fp32 once (36 regs) ----
    float Tf[6][6];
    #pragma unroll
    for (int nt = 0; nt < 6; nt++) {
        const int qp = ng * 24 + nt * 4 + c;
        uint4 tv = *(const uint4*)(smem + SM_T + ebase * 832 + qp * 16);
        float2 u0 = __half22float2(*(half2*)&tv.x);
        float2 u1 = __half22float2(*(half2*)&tv.y);
        float2 u2 = __half22float2(*(half2*)&tv.z);
        float2 u3 = __half22float2(*(half2*)&tv.w);
        Tf[nt][0] = u0.x; Tf[nt][1] = u0.y; Tf[nt][2] = u1.x;
        Tf[nt][3] = u2.x; Tf[nt][4] = u2.y; Tf[nt][5] = u3.x;
    }

    float* ped = (float*)(smem + SM_PED);

    for (int o = 0; o < NCHUNK; o++) {
        // stage next chunk via cp.async (buffer freed by previous sync)
        if (o + 1 < NCHUNK) {
            const uint32_t dst = smem_u32 + SM_B + ((o + 1) & 1) * 12288;
            const float4* src = gB4 + (size_t)(o + 1) * 768;
            cp_async16(dst + tid * 16, src + tid);
            if (tid < 256)
                cp_async16(dst + (512 + tid) * 16, src + 512 + tid);
            asm volatile("cp.async.commit_group;" ::: "memory");
        }

        const char* buf = smem + SM_B + (o & 1) * 12288 + ng * 6144;
        float C[6][4];
        #pragma unroll
        for (int nt = 0; nt < 6; nt++) {
            C[nt][0] = 0.f; C[nt][1] = 0.f; C[nt][2] = 0.f; C[nt][3] = 0.f;
        }

        #pragma unroll
        for (int kt = 0; kt < 4; kt++) {
            uint4 bh[3];
            #pragma unroll
            for (int jj = 0; jj < 3; jj++)
                bh[jj] = *(const uint4*)(buf + (kt*3 + jj) * 512 + lane * 16);
            #pragma unroll
            for (int jj = 0; jj < 3; jj++) {
                mma16816(C[2*jj],   A[kt], bh[jj].x, bh[jj].y);
                mma16816(C[2*jj+1], A[kt], bh[jj].z, bh[jj].w);
            }
        }

        // ---- epilogue: s=0 from register cache, s=1 from smem ----
        float acc[2][3];
        acc[0][0]=0.f; acc[0][1]=0.f; acc[0][2]=0.f;
        acc[1][0]=0.f; acc[1][1]=0.f; acc[1][2]=0.f;

        #pragma unroll
        for (int nt = 0; nt < 6; nt++) {
            const float cA0 = C[nt][0], cB0 = C[nt][1];
            acc[0][0] = fmaf(cA0, Tf[nt][0], fmaf(cB0, Tf[nt][3], acc[0][0]));
            acc[0][1] = fmaf(cA0, Tf[nt][1], fmaf(cB0, Tf[nt][4], acc[0][1]));
            acc[0][2] = fmaf(cA0, Tf[nt][2], fmaf(cB0, Tf[nt][5], acc[0][2]));

            const int qp = ng * 24 + nt * 4 + c;
            uint4 tv = *(const uint4*)(smem + SM_T + (ebase + 8) * 832 + qp * 16);
            float2 u0 = __half22float2(*(half2*)&tv.x);
            float2 u1 = __half22float2(*(half2*)&tv.y);
            float2 u2 = __half22float2(*(half2*)&tv.z);
            float2 u3 = __half22float2(*(half2*)&tv.w);
            const float cA1 = C[nt][2], cB1 = C[nt][3];
            acc[1][0] = fmaf(cA1, u0.x, fmaf(cB1, u2.x, acc[1][0]));
            acc[1][1] = fmaf(cA1, u0.y, fmaf(cB1, u2.y, acc[1][1]));
            acc[1][2] = fmaf(cA1, u1.x, fmaf(cB1, u3.x, acc[1][2]));
        }
        #pragma unroll
        for (int s = 0; s < 2; s++) {
            #pragma unroll
            for (int m = 0; m < 3; m++) {
                acc[s][m] += __shfl_xor_sync(0xffffffffu, acc[s][m], 1);
                acc[s][m] += __shfl_xor_sync(0xffffffffu, acc[s][m], 2);
            }
        }

        // ng=1 publishes partials (parity o&1)
        if (ng == 1 && c == 0) {
            float* p = ped + (o & 1) * 384 + (eg * 8 + r) * 6;
            p[0] = acc[0][0]; p[1] = acc[0][1]; p[2] = acc[0][2];
            p[3] = acc[1][0]; p[4] = acc[1][1]; p[5] = acc[1][2];
        }

        asm volatile("cp.async.wait_group 0;" ::: "memory");
        __syncthreads();

        // ng=0 combines + stores
        if (ng == 0 && c == 0) {
            const float* p = ped + (o & 1) * 384 + (eg * 8 + r) * 6;
            float* op0 = out + (size_t)(E0 + ebase) * (NCOUT * MO) + o * 3;
            op0[0] = acc[0][0] + p[0];
            op0[1] = acc[0][1] + p[1];
            op0[2] = acc[0][2] + p[2];
            float* op1 = out + (size_t)(E0 + ebase + 8) * (NCOUT * MO) + o * 3;
            op1[0] = acc[1][0] + p[3];
            op1[1] = acc[1][1] + p[4];
            op1[2] = acc[1][2] + p[5];
        }
    }
}

// ---------------- launch ----------------
extern "C" void kernel_launch(void* const* d_in, const int* in_sizes, int n_in,
                              void* d_out, int out_size) {
    const float* edges = (const float*)d_in[0];
    const float* feats = (const float*)d_in[1];
    const float* basis = (const float*)d_in[2];
    const float* W1    = (const float*)d_in[3];
    const float* b1    = (const float*)d_in[4];
    const float* g1    = (const float*)d_in[5];
    const float* be1   = (const float*)d_in[6];
    const float* W2    = (const float*)d_in[7];
    const float* b2    = (const float*)d_in[8];
    const float* g2    = (const float*)d_in[9];
    const float* be2   = (const float*)d_in[10];
    const float* W3    = (const float*)d_in[11];
    float* out = (float*)d_out;

    const int E = in_sizes[0] / EDGE_DIM;

    prep_w3<<<(MID * RADW + 255) / 256, 256>>>(W3);

    cudaFuncSetAttribute(pair_main_kernel,
                         cudaFuncAttributeMaxDynamicSharedMemorySize, SM_TOTAL);
    pair_main_kernel<<<E / 128, 512, SM_TOTAL>>>(edges, feats, basis,
                                                 W1, b1, g1, be1,
                                                 W2, b2, g2, be2, out, E);
}

// round 14
// speedup vs baseline: 1.6448x; 1.0270x over previous
#include <cuda_runtime.h>
#include <cuda_fp16.h>
#include <cstdint>

// ---------------- problem constants ----------------
#define EDGE_DIM 32
#define MID      64
#define NCIN     32
#define NCOUT    32
#define MO       3
#define QDIM     96
#define RADW     3072
#define EMAX     32768
#define NCHUNK   32
#define HP       68            // h smem pitch (floats)

// scratch: per chunk 12288 B fragment-register-order fp16 W3 image
__device__ __half g_B[NCHUNK * 12288 / 2];

// ---------------- helpers ----------------
__device__ __forceinline__ float gelu_exact(float x) {
    return 0.5f * x * (1.0f + erff(x * 0.70710678118654752440f));
}
__device__ __forceinline__ float warp_allreduce_sum(float v) {
    v += __shfl_xor_sync(0xffffffffu, v, 16);
    v += __shfl_xor_sync(0xffffffffu, v, 8);
    v += __shfl_xor_sync(0xffffffffu, v, 4);
    v += __shfl_xor_sync(0xffffffffu, v, 2);
    v += __shfl_xor_sync(0xffffffffu, v, 1);
    return v;
}
__device__ __forceinline__ uint32_t pack_h2(float x, float y) {
    half2 h = __floats2half2_rn(x, y);
    return *(uint32_t*)&h;
}
__device__ __forceinline__ void mma16816(float c[4], const uint32_t a[4],
                                         uint32_t b0, uint32_t b1) {
    asm volatile(
        "mma.sync.aligned.m16n8k16.row.col.f32.f16.f16.f32 "
        "{%0,%1,%2,%3}, {%4,%5,%6,%7}, {%8,%9}, {%0,%1,%2,%3};"
        : "+f"(c[0]), "+f"(c[1]), "+f"(c[2]), "+f"(c[3])
        : "r"(a[0]), "r"(a[1]), "r"(a[2]), "r"(a[3]), "r"(b0), "r"(b1));
}
__device__ __forceinline__ void cp_async16(uint32_t smem_dst, const void* gsrc) {
    asm volatile("cp.async.cg.shared.global [%0], [%1], 16;"
                 :: "r"(smem_dst), "l"(gsrc) : "memory");
}

// ---------------- Kernel P: W3 -> fragment-register-order fp16 image ----------
__global__ void __launch_bounds__(256) prep_w3(const float* __restrict__ W3) {
    int idx = blockIdx.x * 256 + threadIdx.x;     // over 64*3072
    if (idx >= MID * RADW) return;
    int k = idx / RADW, n = idx % RADW;
    int chunk = n / QDIM, nl = n % QDIM;
    int ng = nl / 48, nq = nl % 48;
    int nt = nq >> 3, rr = nq & 7;
    int kt = k >> 4, kk = k & 15;
    int cc = (kk >> 1) & 3, bb = kk >> 3, hp = kk & 1;
    int lane = rr * 4 + cc;
    int j = kt * 3 + (nt >> 1);
    int r4 = ((nt & 1) << 1) + bb;
    int off = chunk * 12288 + ng * 6144 + j * 512 + lane * 16 + r4 * 4 + hp * 2;
    g_B[off >> 1] = __float2half_rn(W3[idx]);
}

// ---------------- Kernel M: fused MLP + mma.sync, paired chunks ----------------
// 512 thr / 16 warps = 8 edge-groups x 2 n-halves; 128 edges per CTA.
// B ring: 4 x 12288; one sync per 2 chunks.
#define SM_B     0                          // 4 x 12288 = 49152
#define SM_T     49152                      // 128 x 832 = 106496 -> 155648
#define SM_PED   155648                     // 2 parity x 768 floats = 6144 -> 161792
#define SM_W     161792                     // 6528 floats = 26112 -> 187904
#define SM_H     187904                     // 128 x 68 x 4 = 34816 -> 222720
#define SM_TOTAL 222720

__global__ void __launch_bounds__(512, 1) pair_main_kernel(
    const float* __restrict__ edges,
    const float* __restrict__ feats,
    const float* __restrict__ basis,
    const float* __restrict__ W1, const float* __restrict__ b1,
    const float* __restrict__ g1, const float* __restrict__ be1,
    const float* __restrict__ W2, const float* __restrict__ b2,
    const float* __restrict__ g2, const float* __restrict__ be2,
    float* __restrict__ out,
    int E)
{
    extern __shared__ __align__(1024) char smem[];
    const uint32_t smem_u32 = (uint32_t)__cvta_generic_to_shared(smem);
    const int tid = threadIdx.x, w = tid >> 5, lane = tid & 31;
    const int r = lane >> 2, c = lane & 3;
    const int eg = w >> 1, ng = w & 1;        // eg in [0,8)
    const int E0 = blockIdx.x * 128;
    const int ebase = eg * 16 + r;

    float* hsm = (float*)(smem + SM_H);
    float* Wsm = (float*)(smem + SM_W);
    float* W1s = Wsm;               // 2048
    float* W2s = Wsm + 2048;        // 4096
    float* prm = Wsm + 6144;        // 384

    const float4* gB4 = (const float4*)g_B;

    // ---- stage chunks 0,1 via cp.async (overlaps all prologue work) ----
    #pragma unroll
    for (int j = 0; j < 3; j++) {
        const int idx = tid + j * 512;          // 0..1535
        const int ch = idx / 768, off = idx - ch * 768;
        cp_async16(smem_u32 + SM_B + ch * 12288 + off * 16, gB4 + ch * 768 + off);
    }
    asm volatile("cp.async.commit_group;" ::: "memory");

    // ---- load MLP weights ----
    for (int i = tid; i < EDGE_DIM * MID; i += 512) W1s[i] = W1[i];
    for (int i = tid; i < MID * MID; i += 512)      W2s[i] = W2[i];
    if (tid < MID) {
        prm[tid] = b1[tid]; prm[MID + tid] = g1[tid]; prm[2*MID + tid] = be1[tid];
        prm[3*MID + tid] = b2[tid]; prm[4*MID + tid] = g2[tid]; prm[5*MID + tid] = be2[tid];
    }

    // ---- T tile: [e][qp] pitch 832; one uint4 = fp16 {t0, t1} ----
    for (int idx = tid; idx < 128 * 48; idx += 512) {
        const int e = idx / 48, qp = idx - e * 48;
        const int q0 = 2 * qp, q1 = q0 + 1;
        const int i0 = q0 / 3, f0 = q0 % 3, i1 = q1 / 3, f1 = q1 % 3;
        const float* fe = feats + (size_t)(E0 + e) * (NCIN * 3);
        const float* be = basis + (size_t)(E0 + e) * 27;
        const float a0 = fe[i0*3], a1 = fe[i0*3+1], a2 = fe[i0*3+2];
        const float b0 = fe[i1*3], b1v = fe[i1*3+1], b2v = fe[i1*3+2];
        float t0[3], t1[3];
        #pragma unroll
        for (int m = 0; m < 3; m++) {
            t0[m] = a0 * be[f0*3+m] + a1  * be[9 + f0*3+m] + a2  * be[18 + f0*3+m];
            t1[m] = b0 * be[f1*3+m] + b1v * be[9 + f1*3+m] + b2v * be[18 + f1*3+m];
        }
        uint4 v;
        v.x = pack_h2(t0[0], t0[1]);
        v.y = pack_h2(t0[2], 0.0f);
        v.z = pack_h2(t1[0], t1[1]);
        v.w = pack_h2(t1[2], 0.0f);
        *(uint4*)(smem + SM_T + e * 832 + qp * 16) = v;
    }
    __syncthreads();    // weights + T visible

    // ---- fused MLP: warp w computes edges [w*8, w*8+8) ----
    for (int it = 0; it < 8; it++) {
        const int el = w * 8 + it;
        const float xv = edges[(size_t)(E0 + el) * EDGE_DIM + lane];
        float a0 = prm[lane], a1 = prm[lane + 32];
        #pragma unroll
        for (int k = 0; k < 32; k++) {
            const float xk = __shfl_sync(0xffffffffu, xv, k);
            a0 = fmaf(xk, W1s[k * MID + lane], a0);
            a1 = fmaf(xk, W1s[k * MID + lane + 32], a1);
        }
        float mean = warp_allreduce_sum(a0 + a1) * (1.0f / 64.0f);
        float d0 = a0 - mean, d1 = a1 - mean;
        float var = warp_allreduce_sum(d0 * d0 + d1 * d1) * (1.0f / 64.0f);
        float inv = rsqrtf(var + 1e-5f);
        a0 = gelu_exact(d0 * inv * prm[MID + lane]      + prm[2*MID + lane]);
        a1 = gelu_exact(d1 * inv * prm[MID + lane + 32] + prm[2*MID + lane + 32]);
        float c0 = prm[3*MID + lane], c1 = prm[3*MID + lane + 32];
        #pragma unroll
        for (int k = 0; k < 32; k++) {
            const float u  = __shfl_sync(0xffffffffu, a0, k);
            const float v2 = __shfl_sync(0xffffffffu, a1, k);
            c0 = fmaf(u,  W2s[k * MID + lane], c0);
            c0 = fmaf(v2, W2s[(k + 32) * MID + lane], c0);
            c1 = fmaf(u,  W2s[k * MID + lane + 32], c1);
            c1 = fmaf(v2, W2s[(k + 32) * MID + lane + 32], c1);
        }
        mean = warp_allreduce_sum(c0 + c1) * (1.0f / 64.0f);
        d0 = c0 - mean; d1 = c1 - mean;
        var = warp_allreduce_sum(d0 * d0 + d1 * d1) * (1.0f / 64.0f);
        inv = rsqrtf(var + 1e-5f);
        c0 = gelu_exact(d0 * inv * prm[4*MID + lane]      + prm[5*MID + lane]);
        c1 = gelu_exact(d1 * inv * prm[4*MID + lane + 32] + prm[5*MID + lane + 32]);
        hsm[el * HP + lane]      = c0;
        hsm[el * HP + lane + 32] = c1;
    }
    asm volatile("cp.async.wait_group 0;" ::: "memory");
    __syncthreads();    // h visible; B chunks 0,1 landed

    // ---- A fragments (16 edges: rows ebase, ebase+8) ----
    uint32_t A[4][4];
    {
        const float* h0 = hsm + ebase * HP;
        const float* h1 = hsm + (ebase + 8) * HP;
        #pragma unroll
        for (int kt = 0; kt < 4; kt++) {
            const int k0 = kt * 16 + 2 * c;
            float2 p0 = *(const float2*)(h0 + k0);
            float2 p1 = *(const float2*)(h0 + k0 + 8);
            float2 p2 = *(const float2*)(h1 + k0);
            float2 p3 = *(const float2*)(h1 + k0 + 8);
            A[kt][0] = pack_h2(p0.x, p0.y);
            A[kt][1] = pack_h2(p2.x, p2.y);
            A[kt][2] = pack_h2(p1.x, p1.y);
            A[kt][3] = pack_h2(p3.x, p3.y);
        }
    }

    // ---- T register cache for s=0, converted to fp32 once (36 regs) ----
    float Tf[6][6];
    #pragma unroll
    for (int nt = 0; nt < 6; nt++) {
        const int qp = ng * 24 + nt * 4 + c;
        uint4 tv = *(const uint4*)(smem + SM_T + ebase * 832 + qp * 16);
        float2 u0 = __half22float2(*(half2*)&tv.x);
        float2 u1 = __half22float2(*(half2*)&tv.y);
        float2 u2 = __half22float2(*(half2*)&tv.z);
        float2 u3 = __half22float2(*(half2*)&tv.w);
        Tf[nt][0] = u0.x; Tf[nt][1] = u0.y; Tf[nt][2] = u1.x;
        Tf[nt][3] = u2.x; Tf[nt][4] = u2.y; Tf[nt][5] = u3.x;
    }

    float* ped = (float*)(smem + SM_PED);

    for (int o = 0; o < NCHUNK; o += 2) {
        // stage next pair via cp.async into the other two ring slots
        if (o + 2 < NCHUNK) {
            #pragma unroll
            for (int j = 0; j < 3; j++) {
                const int idx = tid + j * 512;
                const int ch = idx / 768, off = idx - ch * 768;
                const int gch = o + 2 + ch;
                cp_async16(smem_u32 + SM_B + (gch & 3) * 12288 + off * 16,
                           gB4 + (size_t)gch * 768 + off);
            }
            asm volatile("cp.async.commit_group;" ::: "memory");
        }

        float accP[2][2][3];    // [chunk-in-pair][s][m]
        #pragma unroll
        for (int h = 0; h < 2; h++) {
            const char* buf = smem + SM_B + ((o + h) & 3) * 12288 + ng * 6144;
            float C[6][4];
            #pragma unroll
            for (int nt = 0; nt < 6; nt++) {
                C[nt][0] = 0.f; C[nt][1] = 0.f; C[nt][2] = 0.f; C[nt][3] = 0.f;
            }
            #pragma unroll
            for (int kt = 0; kt < 4; kt++) {
                uint4 bh[3];
                #pragma unroll
                for (int jj = 0; jj < 3; jj++)
                    bh[jj] = *(const uint4*)(buf + (kt*3 + jj) * 512 + lane * 16);
                #pragma unroll
                for (int jj = 0; jj < 3; jj++) {
                    mma16816(C[2*jj],   A[kt], bh[jj].x, bh[jj].y);
                    mma16816(C[2*jj+1], A[kt], bh[jj].z, bh[jj].w);
                }
            }

            float (*acc)[3] = accP[h];
            acc[0][0]=0.f; acc[0][1]=0.f; acc[0][2]=0.f;
            acc[1][0]=0.f; acc[1][1]=0.f; acc[1][2]=0.f;
            #pragma unroll
            for (int nt = 0; nt < 6; nt++) {
                const float cA0 = C[nt][0], cB0 = C[nt][1];
                acc[0][0] = fmaf(cA0, Tf[nt][0], fmaf(cB0, Tf[nt][3], acc[0][0]));
                acc[0][1] = fmaf(cA0, Tf[nt][1], fmaf(cB0, Tf[nt][4], acc[0][1]));
                acc[0][2] = fmaf(cA0, Tf[nt][2], fmaf(cB0, Tf[nt][5], acc[0][2]));

                const int qp = ng * 24 + nt * 4 + c;
                uint4 tv = *(const uint4*)(smem + SM_T + (ebase + 8) * 832 + qp * 16);
                float2 u0 = __half22float2(*(half2*)&tv.x);
                float2 u1 = __half22float2(*(half2*)&tv.y);
                float2 u2 = __half22float2(*(half2*)&tv.z);
                float2 u3 = __half22float2(*(half2*)&tv.w);
                const float cA1 = C[nt][2], cB1 = C[nt][3];
                acc[1][0] = fmaf(cA1, u0.x, fmaf(cB1, u2.x, acc[1][0]));
                acc[1][1] = fmaf(cA1, u0.y, fmaf(cB1, u2.y, acc[1][1]));
                acc[1][2] = fmaf(cA1, u1.x, fmaf(cB1, u3.x, acc[1][2]));
            }
            #pragma unroll
            for (int s = 0; s < 2; s++) {
                #pragma unroll
                for (int m = 0; m < 3; m++) {
                    acc[s][m] += __shfl_xor_sync(0xffffffffu, acc[s][m], 1);
                    acc[s][m] += __shfl_xor_sync(0xffffffffu, acc[s][m], 2);
                }
            }
            // ng=1 publishes both chunks' partials (parity (o>>1)&1)
            if (ng == 1 && c == 0) {
                float* p = ped + ((o >> 1) & 1) * 768 + (eg * 8 + r) * 12 + h * 6;
                p[0] = acc[0][0]; p[1] = acc[0][1]; p[2] = acc[0][2];
                p[3] = acc[1][0]; p[4] = acc[1][1]; p[5] = acc[1][2];
            }
        }

        asm volatile("cp.async.wait_group 0;" ::: "memory");
        __syncthreads();

        // ng=0 combines + stores both chunks
        if (ng == 0 && c == 0) {
            const float* pb = ped + ((o >> 1) & 1) * 768 + (eg * 8 + r) * 12;
            #pragma unroll
            for (int h = 0; h < 2; h++) {
                const float* p = pb + h * 6;
                float* op0 = out + (size_t)(E0 + ebase) * (NCOUT * MO) + (o + h) * 3;
                op0[0] = accP[h][0][0] + p[0];
                op0[1] = accP[h][0][1] + p[1];
                op0[2] = accP[h][0][2] + p[2];
                float* op1 = out + (size_t)(E0 + ebase + 8) * (NCOUT * MO) + (o + h) * 3;
                op1[0] = accP[h][1][0] + p[3];
                op1[1] = accP[h][1][1] + p[4];
                op1[2] = accP[h][1][2] + p[5];
            }
        }
    }
}

// ---------------- launch ----------------
extern "C" void kernel_launch(void* const* d_in, const int* in_sizes, int n_in,
                              void* d_out, int out_size) {
    const float* edges = (const float*)d_in[0];
    const float* feats = (const float*)d_in[1];
    const float* basis = (const float*)d_in[2];
    const float* W1    = (const float*)d_in[3];
    const float* b1    = (const float*)d_in[4];
    const float* g1    = (const float*)d_in[5];
    const float* be1   = (const float*)d_in[6];
    const float* W2    = (const float*)d_in[7];
    const float* b2    = (const float*)d_in[8];
    const float* g2    = (const float*)d_in[9];
    const float* be2   = (const float*)d_in[10];
    const float* W3    = (const float*)d_in[11];
    float* out = (float*)d_out;

    const int E = in_sizes[0] / EDGE_DIM;

    prep_w3<<<(MID * RADW + 255) / 256, 256>>>(W3);

    cudaFuncSetAttribute(pair_main_kernel,
                         cudaFuncAttributeMaxDynamicSharedMemorySize, SM_TOTAL);
    pair_main_kernel<<<E / 128, 512, SM_TOTAL>>>(edges, feats, basis,
                                                 W1, b1, g1, be1,
                                                 W2, b2, g2, be2, out, E);
}